// round 11
// baseline (speedup 1.0000x reference)
#include <cuda_runtime.h>
#include <cuda_fp16.h>
#include <cstdint>

// ---------------------------------------------------------------------------
// Attention_49048526520431 (GB300 sm_103a via compute_103 family target).
//   out[b,d] = sum_k (sum_q softmax(q k^T /16)[q,k]) * v[b,k,d]
// B=16, S=2048, D=256 fp32.
//
// GEMMs: mma.sync.m16n8k16 fp16, fp32 acc; 256 thr / 8 warps (2m x 4n) of
// 64x32; BK=64; 3-stage cp.async pipeline, one barrier per chunk.
//  x  split: [x_hi | x_lo | x_hi] (768);  W split: [W_hi | W_hi | W_lo] (768)
//  q,k proj: K=256 (1-term, x_hi·W_hi)
//  v   proj: K=768 (3-term)
//  energy  : K=256 (q_hi·k_hi); epilogue stores P=exp(e-8) fp16 and
//            accumulates fp32 row sums via smem + global atomics.
//  colsum  : w[k] = sum_q P[q,k]/S_q  (pure stream + FMA, no exp)
// ---------------------------------------------------------------------------

#define KSPLIT 768
#define KPAD 72                /* smem row stride in halves (144B) */
#define SMEM_BYTES (6 * 128 * KPAD * 2)   /* 110592: 3 stages x (A,B) */

__device__ __half g_xs[32768 * KSPLIT];    // [hi | lo | hi]
__device__ __half g_wt[3][256 * KSPLIT];   // q,k,v: [hi | hi | lo]
__device__ __half g_qs[16 * 2048 * 256];   // q hi
__device__ __half g_ks[16 * 2048 * 256];   // k hi
__device__ float  g_v[16 * 2048 * 256];
__device__ __half g_p[67108864];           // P = exp(e-8), fp16
__device__ float  g_rs[16 * 2048];         // row sums of P
__device__ float  g_wp[128 * 2048];        // colsum partials (b x 8 qc)
__device__ float  g_op[128 * 256];         // out partials (b x 8 kc)

// ----------------------------- PTX helpers ---------------------------------
__device__ __forceinline__ uint32_t smem_u32(const void* p) {
    uint32_t a;
    asm("{ .reg .u64 t; cvta.to.shared.u64 t, %1; cvt.u32.u64 %0, t; }" : "=r"(a) : "l"(p));
    return a;
}
__device__ __forceinline__ void cp16(uint32_t s, const void* g) {
    asm volatile("cp.async.cg.shared.global [%0], [%1], 16;" :: "r"(s), "l"(g));
}
#define CP_COMMIT() asm volatile("cp.async.commit_group;" ::: "memory")
#define CP_WAIT(n)  asm volatile("cp.async.wait_group %0;" :: "n"(n) : "memory")

__device__ __forceinline__ void ldmx4(uint32_t a, uint32_t& r0, uint32_t& r1,
                                      uint32_t& r2, uint32_t& r3) {
    asm volatile("ldmatrix.sync.aligned.m8n8.x4.shared.b16 {%0,%1,%2,%3}, [%4];"
                 : "=r"(r0), "=r"(r1), "=r"(r2), "=r"(r3) : "r"(a));
}
__device__ __forceinline__ void mma16816(float* c, uint32_t a0, uint32_t a1,
                                         uint32_t a2, uint32_t a3,
                                         uint32_t b0, uint32_t b1) {
    asm volatile(
        "mma.sync.aligned.m16n8k16.row.col.f32.f16.f16.f32 "
        "{%0,%1,%2,%3}, {%4,%5,%6,%7}, {%8,%9}, {%0,%1,%2,%3};"
        : "+f"(c[0]), "+f"(c[1]), "+f"(c[2]), "+f"(c[3])
        : "r"(a0), "r"(a1), "r"(a2), "r"(a3), "r"(b0), "r"(b1));
}

// ---------------------------------------------------------------------------
// Prep
// ---------------------------------------------------------------------------
__global__ void zero_rs_kernel() {
    g_rs[blockIdx.x * 256 + threadIdx.x] = 0.0f;
}

__global__ void split_x_kernel(const float* __restrict__ x) {
    long long i = (long long)blockIdx.x * 256 + threadIdx.x;
    long long row = i >> 8;
    int col = (int)(i & 255);
    float v = x[i];
    __half hi = __float2half(v);
    __half lo = __float2half(v - __half2float(hi));
    __half* o = g_xs + row * KSPLIT;
    o[col] = hi; o[col + 256] = lo; o[col + 512] = hi;          // [hi|lo|hi]
}

__global__ void split_w_kernel(const float* __restrict__ Wq,
                               const float* __restrict__ Wk,
                               const float* __restrict__ Wv) {
    const int z = blockIdx.y;
    const float* W = (z == 0) ? Wq : (z == 1) ? Wk : Wv;
    int n = blockIdx.x;
    int k = threadIdx.x;
    float v = W[k * 256 + n];                                   // transpose
    __half hi = __float2half(v);
    __half lo = __float2half(v - __half2float(hi));
    __half* o = g_wt[z] + n * KSPLIT;
    o[k] = hi; o[k + 256] = hi; o[k + 512] = lo;                // [hi|hi|lo]
}

// ---------------------------------------------------------------------------
// fp16 HMMA GEMM, 3-stage pipeline, 1 barrier/chunk.
// MODE 0: energy -> P=exp(e-8) fp16 + rowsums (batched z).
// MODE 1: v -> Cf fp32 (+bias).
// MODE 2: q/k -> Ch fp16 (+bias); z selects (B,bias,out) pair.
// ---------------------------------------------------------------------------
template <int MODE, int KLEN>
__global__ __launch_bounds__(256, 2) void hmma_gemm(
    const __half* __restrict__ A, const __half* __restrict__ B,
    const float* __restrict__ bias, float* __restrict__ Cf,
    __half* __restrict__ Ch,
    const __half* __restrict__ B2, const float* __restrict__ bias2,
    __half* __restrict__ Ch2,
    long long lda, long long ldb, long long strideA, long long strideB,
    float scale)
{
    extern __shared__ __align__(128) unsigned char dyn[];
    __shared__ float srow[128];

    const int tid = threadIdx.x;
    const int lid = tid & 31;
    const int wid = tid >> 5;
    const int wm = (wid & 1) * 64;       // 2 m-slots
    const int wn = (wid >> 1) * 32;      // 4 n-slots
    const int n0 = blockIdx.x * 128;
    const int m0 = blockIdx.y * 128;
    if (MODE == 2 && blockIdx.z) { B = B2; bias = bias2; Ch = Ch2; }
    if (MODE == 0) {
        A += (long long)blockIdx.z * strideA;
        B += (long long)blockIdx.z * strideB;
        if (tid < 128) srow[tid] = 0.0f;
    }

    const int lr = tid >> 3;             // 0..31 base row for loads
    const int lc = (tid & 7) * 8;        // col in halves

    float acc[4][4][4];
#pragma unroll
    for (int i = 0; i < 4; i++)
#pragma unroll
        for (int j = 0; j < 4; j++)
#pragma unroll
            for (int q = 0; q < 4; q++) acc[i][j][q] = 0.0f;

    uint32_t sAb[3], sBb[3];
#pragma unroll
    for (int s = 0; s < 3; s++) {
        sAb[s] = smem_u32(dyn + (2 * s) * 128 * KPAD * 2);
        sBb[s] = smem_u32(dyn + (2 * s + 1) * 128 * KPAD * 2);
    }

    const int xrow = lid & 15;
    const int xcol = (lid >> 4) * 8;
    const int NC = KLEN / 64;

    auto load_chunk = [&](int c) {
        const int k0 = c * 64;
        const int b = c % 3;
#pragma unroll
        for (int i = 0; i < 4; i++) {
            int r = lr + i * 32;
            cp16(sAb[b] + (r * KPAD + lc) * 2, A + (long long)(m0 + r) * lda + k0 + lc);
            cp16(sBb[b] + (r * KPAD + lc) * 2, B + (long long)(n0 + r) * ldb + k0 + lc);
        }
    };

    load_chunk(0); CP_COMMIT();
    if (NC > 1) { load_chunk(1); CP_COMMIT(); }

    for (int c = 0; c < NC; c++) {
        if (c + 1 < NC) CP_WAIT(1); else CP_WAIT(0);
        __syncthreads();                 // single barrier per chunk
        const int b = c % 3;
#pragma unroll
        for (int kf = 0; kf < 4; kf++) {
            uint32_t a[4][4];
#pragma unroll
            for (int mf = 0; mf < 4; mf++)
                ldmx4(sAb[b] + ((wm + mf * 16 + xrow) * KPAD + kf * 16 + xcol) * 2,
                      a[mf][0], a[mf][1], a[mf][2], a[mf][3]);
            uint32_t bp[4][2];
#pragma unroll
            for (int np = 0; np < 2; np++) {
                uint32_t r0, r1, r2, r3;
                ldmx4(sBb[b] + ((wn + np * 16 + xrow) * KPAD + kf * 16 + xcol) * 2,
                      r0, r1, r2, r3);
                bp[np * 2 + 0][0] = r0; bp[np * 2 + 0][1] = r2;
                bp[np * 2 + 1][0] = r1; bp[np * 2 + 1][1] = r3;
            }
#pragma unroll
            for (int mf = 0; mf < 4; mf++)
#pragma unroll
                for (int nf = 0; nf < 4; nf++)
                    mma16816(acc[mf][nf], a[mf][0], a[mf][1], a[mf][2], a[mf][3],
                             bp[nf][0], bp[nf][1]);
        }
        if (c + 2 < NC) { load_chunk(c + 2); CP_COMMIT(); }
    }

    // ------------------------------ epilogue -------------------------------
#pragma unroll
    for (int mf = 0; mf < 4; mf++) {
        float rs_lo = 0.0f, rs_hi = 0.0f;          // MODE 0 rowsum pieces
#pragma unroll
        for (int nf = 0; nf < 4; nf++) {
            const int cc = wn + nf * 8 + (lid & 3) * 2;
            const int n = n0 + cc;
            const int r = wm + mf * 16 + (lid >> 2);
            float v0 = acc[mf][nf][0] * scale;
            float v1 = acc[mf][nf][1] * scale;
            float v2 = acc[mf][nf][2] * scale;
            float v3 = acc[mf][nf][3] * scale;
            if (MODE != 0) {
                float b0 = bias[n], b1 = bias[n + 1];
                v0 += b0; v1 += b1; v2 += b0; v3 += b1;
            }
            const long long m = m0 + r;
            if (MODE == 0) {
                float p0 = __expf(v0 - 8.0f), p1 = __expf(v1 - 8.0f);
                float p2 = __expf(v2 - 8.0f), p3 = __expf(v3 - 8.0f);
                rs_lo += p0 + p1; rs_hi += p2 + p3;
                __half* p = Ch + ((long long)blockIdx.z * 2048 + m) * 2048 + n;
                *(__half2*)p = __floats2half2_rn(p0, p1);
                *(__half2*)(p + 8 * 2048) = __floats2half2_rn(p2, p3);
            } else if (MODE == 1) {
                float* p = Cf + m * 256 + n;
                *(float2*)p = make_float2(v0, v1);
                *(float2*)(p + 8 * 256) = make_float2(v2, v3);
            } else {
                __half* p = Ch + m * 256 + n;
                *(__half2*)p = __halves2half2(__float2half(v0), __float2half(v1));
                *(__half2*)(p + 8 * 256) = __halves2half2(__float2half(v2), __float2half(v3));
            }
        }
        if (MODE == 0) {
            const int r = wm + mf * 16 + (lid >> 2);
#pragma unroll
            for (int o = 1; o < 4; o <<= 1) {      // reduce 4 lanes per row
                rs_lo += __shfl_xor_sync(0xFFFFFFFFu, rs_lo, o);
                rs_hi += __shfl_xor_sync(0xFFFFFFFFu, rs_hi, o);
            }
            if ((lid & 3) == 0) {
                atomicAdd(&srow[r], rs_lo);
                atomicAdd(&srow[r + 8], rs_hi);
            }
        }
    }
    if (MODE == 0) {
        __syncthreads();
        if (tid < 128)
            atomicAdd(&g_rs[blockIdx.z * 2048 + m0 + tid], srow[tid]);
    }
}

// ---------------------------------------------------------------------------
// Column sums of P scaled by 1/S: pure stream + FMA.
// Block (b, qc): thread owns 8 cols, loops 256 q rows.
// ---------------------------------------------------------------------------
__global__ __launch_bounds__(256) void colsum_kernel() {
    const int b = blockIdx.x;
    const int qc = blockIdx.y;
    const int k0 = threadIdx.x * 8;
    const __half* p = g_p + ((long long)(b * 2048 + qc * 256)) * 2048 + k0;
    const float* rs = g_rs + b * 2048 + qc * 256;
    float acc[8];
#pragma unroll
    for (int i = 0; i < 8; i++) acc[i] = 0.0f;
#pragma unroll 2
    for (int q = 0; q < 256; q++) {
        uint4 u = *(const uint4*)(p + (long long)q * 2048);
        float w = __frcp_rn(rs[q]);
        __half2* hp = (__half2*)&u;
#pragma unroll
        for (int i = 0; i < 4; i++) {
            float2 f = __half22float2(hp[i]);
            acc[i * 2]     = fmaf(f.x, w, acc[i * 2]);
            acc[i * 2 + 1] = fmaf(f.y, w, acc[i * 2 + 1]);
        }
    }
    float* o = g_wp + ((long long)b * 8 + qc) * 2048 + k0;
#pragma unroll
    for (int i = 0; i < 8; i += 4)
        *(float4*)(o + i) = make_float4(acc[i], acc[i + 1], acc[i + 2], acc[i + 3]);
}

// ---------------------------------------------------------------------------
// Final contraction over k-chunks (wreduce folded in via broadcast loads).
// ---------------------------------------------------------------------------
__global__ void out_part_kernel() {
    const int b = blockIdx.x;
    const int kc = blockIdx.y;
    const int d = threadIdx.x;
    const float* wp = g_wp + (long long)b * 8 * 2048 + kc * 256;
    const float* v = g_v + ((long long)b * 2048 + kc * 256) * 256 + d;
    float acc = 0.0f;
#pragma unroll 4
    for (int k = 0; k < 256; k++) {
        float w = 0.0f;
#pragma unroll
        for (int j = 0; j < 8; j++) w += wp[j * 2048 + k];
        acc = fmaf(w, v[(long long)k * 256], acc);
    }
    g_op[((long long)b * 8 + kc) * 256 + d] = acc;
}

__global__ void out_reduce_kernel(float* __restrict__ out) {
    const int b = blockIdx.x;
    const int d = threadIdx.x;
    float s = 0.0f;
#pragma unroll
    for (int j = 0; j < 8; j++) s += g_op[((long long)b * 8 + j) * 256 + d];
    out[b * 256 + d] = s;
}

// ---------------------------------------------------------------------------
extern "C" void kernel_launch(void* const* d_in, const int* in_sizes, int n_in,
                              void* d_out, int out_size) {
    (void)in_sizes; (void)n_in; (void)out_size;
    const float* x  = (const float*)d_in[0];
    const float* Wq = (const float*)d_in[1];
    const float* bq = (const float*)d_in[2];
    const float* Wk = (const float*)d_in[3];
    const float* bk = (const float*)d_in[4];
    const float* Wv = (const float*)d_in[5];
    const float* bv = (const float*)d_in[6];
    float* out = (float*)d_out;

    __half *pxs, *pwt, *pqs, *pks, *pp;
    float *pv;
    cudaGetSymbolAddress((void**)&pxs, g_xs);
    cudaGetSymbolAddress((void**)&pwt, g_wt);
    cudaGetSymbolAddress((void**)&pqs, g_qs);
    cudaGetSymbolAddress((void**)&pks, g_ks);
    cudaGetSymbolAddress((void**)&pv, g_v);
    cudaGetSymbolAddress((void**)&pp, g_p);
    __half* pwtq = pwt;
    __half* pwtk = pwt + 256 * KSPLIT;
    __half* pwtv = pwt + 2 * 256 * KSPLIT;

    static int attr_done = 0;
    if (!attr_done) {
        cudaFuncSetAttribute(hmma_gemm<0, 256>, cudaFuncAttributeMaxDynamicSharedMemorySize, SMEM_BYTES);
        cudaFuncSetAttribute(hmma_gemm<1, 768>, cudaFuncAttributeMaxDynamicSharedMemorySize, SMEM_BYTES);
        cudaFuncSetAttribute(hmma_gemm<2, 256>, cudaFuncAttributeMaxDynamicSharedMemorySize, SMEM_BYTES);
        attr_done = 1;
    }

    // 0) zero rowsums; 1) splits
    zero_rs_kernel<<<128, 256>>>();
    split_x_kernel<<<32768, 256>>>(x);
    split_w_kernel<<<dim3(256, 3), 256>>>(Wq, Wk, Wv);

    // 2) projections: q+k combined (K=256, 1-term), v (K=768, 3-term)
    hmma_gemm<2, 256><<<dim3(2, 256, 2), 256, SMEM_BYTES>>>(
        pxs, pwtq, bq, nullptr, pqs, pwtk, bk, pks,
        KSPLIT, KSPLIT, 0, 0, 1.0f);
    hmma_gemm<1, 768><<<dim3(2, 256, 1), 256, SMEM_BYTES>>>(
        pxs, pwtv, bv, pv, nullptr, nullptr, nullptr, nullptr,
        KSPLIT, KSPLIT, 0, 0, 1.0f);

    // 3) energy -> P = exp(e-8) + rowsums, batched, K=256
    hmma_gemm<0, 256><<<dim3(16, 16, 16), 256, SMEM_BYTES>>>(
        pqs, pks, nullptr, nullptr, pp, nullptr, nullptr, nullptr,
        256, 256, (long long)2048 * 256, (long long)2048 * 256, 0.0625f);

    // 4) streaming weighted column sums
    colsum_kernel<<<dim3(16, 8), 256>>>();

    // 5) final contraction (wreduce folded into out_part)
    out_part_kernel<<<dim3(16, 8), 256>>>();
    out_reduce_kernel<<<16, 256>>>(out);
}

// round 12
// speedup vs baseline: 1.2939x; 1.2939x over previous
#include <cuda_runtime.h>
#include <cuda_fp16.h>
#include <cstdint>

// ---------------------------------------------------------------------------
// Attention_49048526520431 (GB300 sm_103a via compute_103 family target).
//   out[b,d] = sum_k (sum_q softmax(q k^T /16)[q,k]) * v[b,k,d]
// B=16, S=2048, D=256 fp32.
//
// GEMMs: mma.sync.m16n8k16 fp16, fp32 acc; 256 thr / 8 warps (2m x 4n) of
// 64x32; BK=64; 3-stage cp.async pipeline, one barrier per chunk.
//  x  split: [x_hi | x_lo | x_hi] (768);  W split: [W_hi | W_hi | W_lo] (768)
//  q,k proj: K=256 (1-term, x_hi·W_hi)
//  v   proj: K=768 (3-term)
//  energy  : K=256 (q_hi·k_hi) -> fp16 e store (minimal epilogue)
// Fused colsum: p=exp(e-8) single pass (no max; offset cancels in softmax).
// ---------------------------------------------------------------------------

#define KSPLIT 768
#define KPAD 72                /* smem row stride in halves (144B) */
#define SMEM_BYTES (6 * 128 * KPAD * 2)   /* 110592: 3 stages x (A,B) */

__device__ __half g_xs[32768 * KSPLIT];    // [hi | lo | hi]
__device__ __half g_wt[3][256 * KSPLIT];   // q,k,v: [hi | hi | lo]
__device__ __half g_qs[16 * 2048 * 256];   // q hi
__device__ __half g_ks[16 * 2048 * 256];   // k hi
__device__ float  g_v[16 * 2048 * 256];
__device__ __half g_energy[67108864];      // 16 * 2048 * 2048 fp16
__device__ float  g_wp[128 * 2048];        // colsum partials (b x 8 qc)
__device__ float  g_w[16 * 2048];
__device__ float  g_op[128 * 256];         // out partials (b x 8 kc)

// ----------------------------- PTX helpers ---------------------------------
__device__ __forceinline__ uint32_t smem_u32(const void* p) {
    uint32_t a;
    asm("{ .reg .u64 t; cvta.to.shared.u64 t, %1; cvt.u32.u64 %0, t; }" : "=r"(a) : "l"(p));
    return a;
}
__device__ __forceinline__ void cp16(uint32_t s, const void* g) {
    asm volatile("cp.async.cg.shared.global [%0], [%1], 16;" :: "r"(s), "l"(g));
}
#define CP_COMMIT() asm volatile("cp.async.commit_group;" ::: "memory")
#define CP_WAIT(n)  asm volatile("cp.async.wait_group %0;" :: "n"(n) : "memory")

__device__ __forceinline__ void ldmx4(uint32_t a, uint32_t& r0, uint32_t& r1,
                                      uint32_t& r2, uint32_t& r3) {
    asm volatile("ldmatrix.sync.aligned.m8n8.x4.shared.b16 {%0,%1,%2,%3}, [%4];"
                 : "=r"(r0), "=r"(r1), "=r"(r2), "=r"(r3) : "r"(a));
}
__device__ __forceinline__ void mma16816(float* c, uint32_t a0, uint32_t a1,
                                         uint32_t a2, uint32_t a3,
                                         uint32_t b0, uint32_t b1) {
    asm volatile(
        "mma.sync.aligned.m16n8k16.row.col.f32.f16.f16.f32 "
        "{%0,%1,%2,%3}, {%4,%5,%6,%7}, {%8,%9}, {%0,%1,%2,%3};"
        : "+f"(c[0]), "+f"(c[1]), "+f"(c[2]), "+f"(c[3])
        : "r"(a0), "r"(a1), "r"(a2), "r"(a3), "r"(b0), "r"(b1));
}

// ---------------------------------------------------------------------------
// Split prep
// ---------------------------------------------------------------------------
__global__ void split_x_kernel(const float* __restrict__ x) {
    long long i = (long long)blockIdx.x * 256 + threadIdx.x;
    long long row = i >> 8;
    int col = (int)(i & 255);
    float v = x[i];
    __half hi = __float2half(v);
    __half lo = __float2half(v - __half2float(hi));
    __half* o = g_xs + row * KSPLIT;
    o[col] = hi; o[col + 256] = lo; o[col + 512] = hi;          // [hi|lo|hi]
}

__global__ void split_w_kernel(const float* __restrict__ Wq,
                               const float* __restrict__ Wk,
                               const float* __restrict__ Wv) {
    const int z = blockIdx.y;
    const float* W = (z == 0) ? Wq : (z == 1) ? Wk : Wv;
    int n = blockIdx.x;
    int k = threadIdx.x;
    float v = W[k * 256 + n];                                   // transpose
    __half hi = __float2half(v);
    __half lo = __float2half(v - __half2float(hi));
    __half* o = g_wt[z] + n * KSPLIT;
    o[k] = hi; o[k + 256] = hi; o[k + 512] = lo;                // [hi|hi|lo]
}

// ---------------------------------------------------------------------------
// fp16 HMMA GEMM, 3-stage pipeline, 1 barrier/chunk.
// MODE 0: energy -> Ch fp16 stride 2048 (batched z), minimal epilogue.
// MODE 1: v -> Cf fp32 (+bias).
// MODE 2: q/k -> Ch fp16 (+bias); z selects (B,bias,out) pair.
// ---------------------------------------------------------------------------
template <int MODE, int KLEN>
__global__ __launch_bounds__(256, 2) void hmma_gemm(
    const __half* __restrict__ A, const __half* __restrict__ B,
    const float* __restrict__ bias, float* __restrict__ Cf,
    __half* __restrict__ Ch,
    const __half* __restrict__ B2, const float* __restrict__ bias2,
    __half* __restrict__ Ch2,
    long long lda, long long ldb, long long strideA, long long strideB,
    float scale)
{
    extern __shared__ __align__(128) unsigned char dyn[];

    const int tid = threadIdx.x;
    const int lid = tid & 31;
    const int wid = tid >> 5;
    const int wm = (wid & 1) * 64;       // 2 m-slots
    const int wn = (wid >> 1) * 32;      // 4 n-slots
    const int n0 = blockIdx.x * 128;
    const int m0 = blockIdx.y * 128;
    if (MODE == 2 && blockIdx.z) { B = B2; bias = bias2; Ch = Ch2; }
    if (MODE == 0) {
        A += (long long)blockIdx.z * strideA;
        B += (long long)blockIdx.z * strideB;
    }

    const int lr = tid >> 3;             // 0..31 base row for loads
    const int lc = (tid & 7) * 8;        // col in halves

    float acc[4][4][4];
#pragma unroll
    for (int i = 0; i < 4; i++)
#pragma unroll
        for (int j = 0; j < 4; j++)
#pragma unroll
            for (int q = 0; q < 4; q++) acc[i][j][q] = 0.0f;

    uint32_t sAb[3], sBb[3];
#pragma unroll
    for (int s = 0; s < 3; s++) {
        sAb[s] = smem_u32(dyn + (2 * s) * 128 * KPAD * 2);
        sBb[s] = smem_u32(dyn + (2 * s + 1) * 128 * KPAD * 2);
    }

    const int xrow = lid & 15;
    const int xcol = (lid >> 4) * 8;
    const int NC = KLEN / 64;

    auto load_chunk = [&](int c) {
        const int k0 = c * 64;
        const int b = c % 3;
#pragma unroll
        for (int i = 0; i < 4; i++) {
            int r = lr + i * 32;
            cp16(sAb[b] + (r * KPAD + lc) * 2, A + (long long)(m0 + r) * lda + k0 + lc);
            cp16(sBb[b] + (r * KPAD + lc) * 2, B + (long long)(n0 + r) * ldb + k0 + lc);
        }
    };

    load_chunk(0); CP_COMMIT();
    if (NC > 1) { load_chunk(1); CP_COMMIT(); }

    for (int c = 0; c < NC; c++) {
        if (c + 1 < NC) CP_WAIT(1); else CP_WAIT(0);
        __syncthreads();                 // single barrier per chunk
        const int b = c % 3;
#pragma unroll
        for (int kf = 0; kf < 4; kf++) {
            uint32_t a[4][4];
#pragma unroll
            for (int mf = 0; mf < 4; mf++)
                ldmx4(sAb[b] + ((wm + mf * 16 + xrow) * KPAD + kf * 16 + xcol) * 2,
                      a[mf][0], a[mf][1], a[mf][2], a[mf][3]);
            uint32_t bp[4][2];
#pragma unroll
            for (int np = 0; np < 2; np++) {
                uint32_t r0, r1, r2, r3;
                ldmx4(sBb[b] + ((wn + np * 16 + xrow) * KPAD + kf * 16 + xcol) * 2,
                      r0, r1, r2, r3);
                bp[np * 2 + 0][0] = r0; bp[np * 2 + 0][1] = r2;
                bp[np * 2 + 1][0] = r1; bp[np * 2 + 1][1] = r3;
            }
#pragma unroll
            for (int mf = 0; mf < 4; mf++)
#pragma unroll
                for (int nf = 0; nf < 4; nf++)
                    mma16816(acc[mf][nf], a[mf][0], a[mf][1], a[mf][2], a[mf][3],
                             bp[nf][0], bp[nf][1]);
        }
        if (c + 2 < NC) { load_chunk(c + 2); CP_COMMIT(); }
    }

    // ------------------------------ epilogue -------------------------------
#pragma unroll
    for (int mf = 0; mf < 4; mf++) {
#pragma unroll
        for (int nf = 0; nf < 4; nf++) {
            const int cc = wn + nf * 8 + (lid & 3) * 2;
            const int n = n0 + cc;
            const int r = wm + mf * 16 + (lid >> 2);
            float v0 = acc[mf][nf][0] * scale;
            float v1 = acc[mf][nf][1] * scale;
            float v2 = acc[mf][nf][2] * scale;
            float v3 = acc[mf][nf][3] * scale;
            if (MODE != 0) {
                float b0 = bias[n], b1 = bias[n + 1];
                v0 += b0; v1 += b1; v2 += b0; v3 += b1;
            }
            const long long m = m0 + r;
            if (MODE == 0) {
                __half* p = Ch + ((long long)blockIdx.z * 2048 + m) * 2048 + n;
                *(__half2*)p = __halves2half2(__float2half(v0), __float2half(v1));
                *(__half2*)(p + 8 * 2048) = __halves2half2(__float2half(v2), __float2half(v3));
            } else if (MODE == 1) {
                float* p = Cf + m * 256 + n;
                *(float2*)p = make_float2(v0, v1);
                *(float2*)(p + 8 * 256) = make_float2(v2, v3);
            } else {
                __half* p = Ch + m * 256 + n;
                *(__half2*)p = __halves2half2(__float2half(v0), __float2half(v1));
                *(__half2*)(p + 8 * 256) = __halves2half2(__float2half(v2), __float2half(v3));
            }
        }
    }
}

// ---------------------------------------------------------------------------
// Fused softmax colsum, no max pass: p = exp(e-8) safe for |e| <~ 10.
// Block = (b, qc): 8 warps, one warp per row, 32 rows/warp.
// ---------------------------------------------------------------------------
__global__ __launch_bounds__(256) void colsum_fused_kernel() {
    const int b = blockIdx.x;
    const int qc = blockIdx.y;
    const int tid = threadIdx.x;
    const int wid = tid >> 5;
    const int lid = tid & 31;

    __shared__ float sacc[2048];
    for (int i = tid; i < 2048; i += 256) sacc[i] = 0.0f;
    __syncthreads();

    float acc[8][8];
#pragma unroll
    for (int i = 0; i < 8; i++)
#pragma unroll
        for (int j = 0; j < 8; j++) acc[i][j] = 0.0f;

    const __half* ebase = g_energy + ((long long)(b * 2048 + qc * 256)) * 2048;

    for (int r = wid; r < 256; r += 8) {
        const uint4* rp = (const uint4*)(ebase + (long long)r * 2048);
        uint4 u[8];
#pragma unroll
        for (int i = 0; i < 8; i++) u[i] = rp[lid + 32 * i];

        float s = 0.0f;
#pragma unroll
        for (int i = 0; i < 8; i++) {
            __half2* hp = (__half2*)&u[i];
#pragma unroll
            for (int j = 0; j < 4; j++) {
                float2 p = __half22float2(hp[j]);
                float e0 = __expf(p.x - 8.0f);
                float e1 = __expf(p.y - 8.0f);
                s += e0 + e1;
                hp[j] = __floats2half2_rn(e0, e1);
            }
        }
#pragma unroll
        for (int o = 16; o > 0; o >>= 1)
            s += __shfl_xor_sync(0xFFFFFFFFu, s, o);
        const float inv = __frcp_rn(s);

#pragma unroll
        for (int i = 0; i < 8; i++) {
            __half2* hp = (__half2*)&u[i];
#pragma unroll
            for (int j = 0; j < 4; j++) {
                float2 p = __half22float2(hp[j]);
                acc[i][j * 2]     += p.x * inv;
                acc[i][j * 2 + 1] += p.y * inv;
            }
        }
    }

#pragma unroll
    for (int i = 0; i < 8; i++)
#pragma unroll
        for (int j = 0; j < 8; j++)
            atomicAdd(&sacc[(lid + 32 * i) * 8 + j], acc[i][j]);
    __syncthreads();

    float* o = g_wp + ((long long)b * 8 + qc) * 2048;
    for (int i = tid; i < 2048; i += 256) o[i] = sacc[i];
}

__global__ void wreduce_kernel() {
    const int i = blockIdx.x * 256 + threadIdx.x;     // 0..32767
    const int b = i >> 11, k = i & 2047;
    float s = 0.0f;
#pragma unroll
    for (int j = 0; j < 8; j++) s += g_wp[((long long)b * 8 + j) * 2048 + k];
    g_w[i] = s;
}

// ---------------------------------------------------------------------------
// Final contraction, parallel over k-chunks.
// ---------------------------------------------------------------------------
__global__ void out_part_kernel() {
    const int b = blockIdx.x;
    const int kc = blockIdx.y;
    const int d = threadIdx.x;
    const float* w = g_w + b * 2048 + kc * 256;
    const float* v = g_v + ((long long)b * 2048 + kc * 256) * 256 + d;
    float acc = 0.0f;
#pragma unroll 8
    for (int k = 0; k < 256; k++)
        acc = fmaf(w[k], v[(long long)k * 256], acc);
    g_op[((long long)b * 8 + kc) * 256 + d] = acc;
}

__global__ void out_reduce_kernel(float* __restrict__ out) {
    const int b = blockIdx.x;
    const int d = threadIdx.x;
    float s = 0.0f;
#pragma unroll
    for (int j = 0; j < 8; j++) s += g_op[((long long)b * 8 + j) * 256 + d];
    out[b * 256 + d] = s;
}

// ---------------------------------------------------------------------------
extern "C" void kernel_launch(void* const* d_in, const int* in_sizes, int n_in,
                              void* d_out, int out_size) {
    (void)in_sizes; (void)n_in; (void)out_size;
    const float* x  = (const float*)d_in[0];
    const float* Wq = (const float*)d_in[1];
    const float* bq = (const float*)d_in[2];
    const float* Wk = (const float*)d_in[3];
    const float* bk = (const float*)d_in[4];
    const float* Wv = (const float*)d_in[5];
    const float* bv = (const float*)d_in[6];
    float* out = (float*)d_out;

    __half *pxs, *pwt, *pqs, *pks, *pe;
    float *pv;
    cudaGetSymbolAddress((void**)&pxs, g_xs);
    cudaGetSymbolAddress((void**)&pwt, g_wt);
    cudaGetSymbolAddress((void**)&pqs, g_qs);
    cudaGetSymbolAddress((void**)&pks, g_ks);
    cudaGetSymbolAddress((void**)&pv, g_v);
    cudaGetSymbolAddress((void**)&pe, g_energy);
    __half* pwtq = pwt;
    __half* pwtk = pwt + 256 * KSPLIT;
    __half* pwtv = pwt + 2 * 256 * KSPLIT;

    static int attr_done = 0;
    if (!attr_done) {
        cudaFuncSetAttribute(hmma_gemm<0, 256>, cudaFuncAttributeMaxDynamicSharedMemorySize, SMEM_BYTES);
        cudaFuncSetAttribute(hmma_gemm<1, 768>, cudaFuncAttributeMaxDynamicSharedMemorySize, SMEM_BYTES);
        cudaFuncSetAttribute(hmma_gemm<2, 256>, cudaFuncAttributeMaxDynamicSharedMemorySize, SMEM_BYTES);
        attr_done = 1;
    }

    // 1) splits
    split_x_kernel<<<32768, 256>>>(x);
    split_w_kernel<<<dim3(256, 3), 256>>>(Wq, Wk, Wv);

    // 2) projections: q+k combined (K=256, 1-term), v (K=768, 3-term)
    hmma_gemm<2, 256><<<dim3(2, 256, 2), 256, SMEM_BYTES>>>(
        pxs, pwtq, bq, nullptr, pqs, pwtk, bk, pks,
        KSPLIT, KSPLIT, 0, 0, 1.0f);
    hmma_gemm<1, 768><<<dim3(2, 256, 1), 256, SMEM_BYTES>>>(
        pxs, pwtv, bv, pv, nullptr, nullptr, nullptr, nullptr,
        KSPLIT, KSPLIT, 0, 0, 1.0f);

    // 3) energy = q_hi k_hi^T / 16, batched, K=256
    hmma_gemm<0, 256><<<dim3(16, 16, 16), 256, SMEM_BYTES>>>(
        pqs, pks, nullptr, nullptr, pe, nullptr, nullptr, nullptr,
        256, 256, (long long)2048 * 256, (long long)2048 * 256, 0.0625f);

    // 4) fused softmax colsum (single pass, no max), reduce
    colsum_fused_kernel<<<dim3(16, 8), 256>>>();
    wreduce_kernel<<<128, 256>>>();

    // 5) final contraction
    out_part_kernel<<<dim3(16, 8), 256>>>();
    out_reduce_kernel<<<16, 256>>>(out);
}

// round 13
// speedup vs baseline: 1.5720x; 1.2149x over previous
#include <cuda_runtime.h>
#include <cuda_fp16.h>
#include <cstdint>

// ---------------------------------------------------------------------------
// Attention_49048526520431 (GB300 sm_103a via compute_103 family target).
//   out[b,d] = sum_k (sum_q softmax(q k^T /16)[q,k]) * v[b,k,d]
// B=16, S=2048, D=256 fp32.
//
// All GEMMs: mma.sync.m16n8k16 fp16, fp32 acc; 256 thr / 8 warps (2m x 4n)
// of 64x32; BK=64; 3-stage cp.async pipeline, one barrier per chunk.
//  ALL projections 1-term fp16 (q,k,v = x_hi @ W_hi^T + b), K=256.
//  energy: K=256 (q_hi·k_hi) -> fp16 e store (minimal epilogue)
// Fused colsum: p=exp(e-8) single pass (no max; offset cancels in softmax),
// 256 blocks (qc=16) for latency hiding.
// ---------------------------------------------------------------------------

#define KPAD 72                /* smem row stride in halves (144B) */
#define SMEM_BYTES (6 * 128 * KPAD * 2)   /* 110592: 3 stages x (A,B) */

__device__ __half g_xh[32768 * 256];       // x hi
__device__ __half g_wth[3][256 * 256];     // W^T hi: q,k,v
__device__ __half g_qs[16 * 2048 * 256];   // q hi
__device__ __half g_ks[16 * 2048 * 256];   // k hi
__device__ float  g_v[16 * 2048 * 256];
__device__ __half g_energy[67108864];      // 16 * 2048 * 2048 fp16
__device__ float  g_wp[256 * 2048];        // colsum partials (b x 16 qc)
__device__ float  g_w[16 * 2048];
__device__ float  g_op[128 * 256];         // out partials (b x 8 kc)

// ----------------------------- PTX helpers ---------------------------------
__device__ __forceinline__ uint32_t smem_u32(const void* p) {
    uint32_t a;
    asm("{ .reg .u64 t; cvta.to.shared.u64 t, %1; cvt.u32.u64 %0, t; }" : "=r"(a) : "l"(p));
    return a;
}
__device__ __forceinline__ void cp16(uint32_t s, const void* g) {
    asm volatile("cp.async.cg.shared.global [%0], [%1], 16;" :: "r"(s), "l"(g));
}
#define CP_COMMIT() asm volatile("cp.async.commit_group;" ::: "memory")
#define CP_WAIT(n)  asm volatile("cp.async.wait_group %0;" :: "n"(n) : "memory")

__device__ __forceinline__ void ldmx4(uint32_t a, uint32_t& r0, uint32_t& r1,
                                      uint32_t& r2, uint32_t& r3) {
    asm volatile("ldmatrix.sync.aligned.m8n8.x4.shared.b16 {%0,%1,%2,%3}, [%4];"
                 : "=r"(r0), "=r"(r1), "=r"(r2), "=r"(r3) : "r"(a));
}
__device__ __forceinline__ void mma16816(float* c, uint32_t a0, uint32_t a1,
                                         uint32_t a2, uint32_t a3,
                                         uint32_t b0, uint32_t b1) {
    asm volatile(
        "mma.sync.aligned.m16n8k16.row.col.f32.f16.f16.f32 "
        "{%0,%1,%2,%3}, {%4,%5,%6,%7}, {%8,%9}, {%0,%1,%2,%3};"
        : "+f"(c[0]), "+f"(c[1]), "+f"(c[2]), "+f"(c[3])
        : "r"(a0), "r"(a1), "r"(a2), "r"(a3), "r"(b0), "r"(b1));
}

// ---------------------------------------------------------------------------
// Prep: fp32 -> fp16 converts
// ---------------------------------------------------------------------------
__global__ void split_x_kernel(const float* __restrict__ x) {
    const int i = blockIdx.x * 256 + threadIdx.x;       // x4 floats
    float4 v = ((const float4*)x)[i];
    __half2* o = (__half2*)g_xh;
    o[i * 2]     = __floats2half2_rn(v.x, v.y);
    o[i * 2 + 1] = __floats2half2_rn(v.z, v.w);
}

__global__ void split_w_kernel(const float* __restrict__ Wq,
                               const float* __restrict__ Wk,
                               const float* __restrict__ Wv) {
    const int z = blockIdx.y;
    const float* W = (z == 0) ? Wq : (z == 1) ? Wk : Wv;
    int n = blockIdx.x;
    int k = threadIdx.x;
    g_wth[z][n * 256 + k] = __float2half(W[k * 256 + n]);   // transpose
}

// ---------------------------------------------------------------------------
// fp16 HMMA GEMM, 3-stage pipeline, 1 barrier/chunk. K=256 always.
// MODE 0: energy -> fp16 e, stride 2048, batched over z.
// MODE 2: projections; z = 0:q(fp16) 1:k(fp16) 2:v(fp32), all +bias.
// ---------------------------------------------------------------------------
template <int MODE>
__global__ __launch_bounds__(256, 2) void hmma_gemm(
    const __half* __restrict__ A,
    const __half* __restrict__ B0, const __half* __restrict__ B1,
    const __half* __restrict__ B2,
    const float* __restrict__ bias0, const float* __restrict__ bias1,
    const float* __restrict__ bias2,
    float* __restrict__ Cf, __half* __restrict__ Ch0, __half* __restrict__ Ch1,
    long long strideA, long long strideB, float scale)
{
    extern __shared__ __align__(128) unsigned char dyn[];

    const int tid = threadIdx.x;
    const int lid = tid & 31;
    const int wid = tid >> 5;
    const int wm = (wid & 1) * 64;       // 2 m-slots
    const int wn = (wid >> 1) * 32;      // 4 n-slots
    const int n0 = blockIdx.x * 128;
    const int m0 = blockIdx.y * 128;
    const int z = blockIdx.z;

    const __half* B = B0;
    const float* bias = bias0;
    __half* Ch = Ch0;
    if (MODE == 2) {
        if (z == 1) { B = B1; bias = bias1; Ch = Ch1; }
        else if (z == 2) { B = B2; bias = bias2; }
    } else {
        A += (long long)z * strideA;
        B += (long long)z * strideB;
    }

    const int lr = tid >> 3;             // 0..31 base row for loads
    const int lc = (tid & 7) * 8;        // col in halves

    float acc[4][4][4];
#pragma unroll
    for (int i = 0; i < 4; i++)
#pragma unroll
        for (int j = 0; j < 4; j++)
#pragma unroll
            for (int q = 0; q < 4; q++) acc[i][j][q] = 0.0f;

    uint32_t sAb[3], sBb[3];
#pragma unroll
    for (int s = 0; s < 3; s++) {
        sAb[s] = smem_u32(dyn + (2 * s) * 128 * KPAD * 2);
        sBb[s] = smem_u32(dyn + (2 * s + 1) * 128 * KPAD * 2);
    }

    const int xrow = lid & 15;
    const int xcol = (lid >> 4) * 8;
    const int NC = 4;                    // K=256 / 64

    auto load_chunk = [&](int c) {
        const int k0 = c * 64;
        const int b = c % 3;
#pragma unroll
        for (int i = 0; i < 4; i++) {
            int r = lr + i * 32;
            cp16(sAb[b] + (r * KPAD + lc) * 2, A + (long long)(m0 + r) * 256 + k0 + lc);
            cp16(sBb[b] + (r * KPAD + lc) * 2, B + (long long)(n0 + r) * 256 + k0 + lc);
        }
    };

    load_chunk(0); CP_COMMIT();
    load_chunk(1); CP_COMMIT();

    for (int c = 0; c < NC; c++) {
        if (c + 1 < NC) CP_WAIT(1); else CP_WAIT(0);
        __syncthreads();                 // single barrier per chunk
        const int b = c % 3;
#pragma unroll
        for (int kf = 0; kf < 4; kf++) {
            uint32_t a[4][4];
#pragma unroll
            for (int mf = 0; mf < 4; mf++)
                ldmx4(sAb[b] + ((wm + mf * 16 + xrow) * KPAD + kf * 16 + xcol) * 2,
                      a[mf][0], a[mf][1], a[mf][2], a[mf][3]);
            uint32_t bp[4][2];
#pragma unroll
            for (int np = 0; np < 2; np++) {
                uint32_t r0, r1, r2, r3;
                ldmx4(sBb[b] + ((wn + np * 16 + xrow) * KPAD + kf * 16 + xcol) * 2,
                      r0, r1, r2, r3);
                bp[np * 2 + 0][0] = r0; bp[np * 2 + 0][1] = r2;
                bp[np * 2 + 1][0] = r1; bp[np * 2 + 1][1] = r3;
            }
#pragma unroll
            for (int mf = 0; mf < 4; mf++)
#pragma unroll
                for (int nf = 0; nf < 4; nf++)
                    mma16816(acc[mf][nf], a[mf][0], a[mf][1], a[mf][2], a[mf][3],
                             bp[nf][0], bp[nf][1]);
        }
        if (c + 2 < NC) { load_chunk(c + 2); CP_COMMIT(); }
    }

    // ------------------------------ epilogue -------------------------------
#pragma unroll
    for (int mf = 0; mf < 4; mf++) {
#pragma unroll
        for (int nf = 0; nf < 4; nf++) {
            const int cc = wn + nf * 8 + (lid & 3) * 2;
            const int n = n0 + cc;
            const int r = wm + mf * 16 + (lid >> 2);
            float v0 = acc[mf][nf][0] * scale;
            float v1 = acc[mf][nf][1] * scale;
            float v2 = acc[mf][nf][2] * scale;
            float v3 = acc[mf][nf][3] * scale;
            if (MODE == 2) {
                float b0 = bias[n], b1 = bias[n + 1];
                v0 += b0; v1 += b1; v2 += b0; v3 += b1;
            }
            const long long m = m0 + r;
            if (MODE == 0) {
                __half* p = Ch + ((long long)z * 2048 + m) * 2048 + n;
                *(__half2*)p = __halves2half2(__float2half(v0), __float2half(v1));
                *(__half2*)(p + 8 * 2048) = __halves2half2(__float2half(v2), __float2half(v3));
            } else if (z == 2) {
                float* p = Cf + m * 256 + n;
                *(float2*)p = make_float2(v0, v1);
                *(float2*)(p + 8 * 256) = make_float2(v2, v3);
            } else {
                __half* p = Ch + m * 256 + n;
                *(__half2*)p = __halves2half2(__float2half(v0), __float2half(v1));
                *(__half2*)(p + 8 * 256) = __halves2half2(__float2half(v2), __float2half(v3));
            }
        }
    }
}

// ---------------------------------------------------------------------------
// Fused softmax colsum, no max pass: p = exp(e-8) safe for |e| <~ 10.
// Block = (b, qc): 16 qc chunks of 128 rows; 8 warps, one warp per row.
// ---------------------------------------------------------------------------
__global__ __launch_bounds__(256) void colsum_fused_kernel() {
    const int b = blockIdx.x;
    const int qc = blockIdx.y;
    const int tid = threadIdx.x;
    const int wid = tid >> 5;
    const int lid = tid & 31;

    __shared__ float sacc[2048];
    for (int i = tid; i < 2048; i += 256) sacc[i] = 0.0f;
    __syncthreads();

    float acc[8][8];
#pragma unroll
    for (int i = 0; i < 8; i++)
#pragma unroll
        for (int j = 0; j < 8; j++) acc[i][j] = 0.0f;

    const __half* ebase = g_energy + ((long long)(b * 2048 + qc * 128)) * 2048;

    for (int r = wid; r < 128; r += 8) {
        const uint4* rp = (const uint4*)(ebase + (long long)r * 2048);
        uint4 u[8];
#pragma unroll
        for (int i = 0; i < 8; i++) u[i] = rp[lid + 32 * i];

        float s = 0.0f;
#pragma unroll
        for (int i = 0; i < 8; i++) {
            __half2* hp = (__half2*)&u[i];
#pragma unroll
            for (int j = 0; j < 4; j++) {
                float2 p = __half22float2(hp[j]);
                float e0 = __expf(p.x - 8.0f);
                float e1 = __expf(p.y - 8.0f);
                s += e0 + e1;
                hp[j] = __floats2half2_rn(e0, e1);
            }
        }
#pragma unroll
        for (int o = 16; o > 0; o >>= 1)
            s += __shfl_xor_sync(0xFFFFFFFFu, s, o);
        const float inv = __frcp_rn(s);

#pragma unroll
        for (int i = 0; i < 8; i++) {
            __half2* hp = (__half2*)&u[i];
#pragma unroll
            for (int j = 0; j < 4; j++) {
                float2 p = __half22float2(hp[j]);
                acc[i][j * 2]     += p.x * inv;
                acc[i][j * 2 + 1] += p.y * inv;
            }
        }
    }

#pragma unroll
    for (int i = 0; i < 8; i++)
#pragma unroll
        for (int j = 0; j < 8; j++)
            atomicAdd(&sacc[(lid + 32 * i) * 8 + j], acc[i][j]);
    __syncthreads();

    float* o = g_wp + ((long long)b * 16 + qc) * 2048;
    for (int i = tid; i < 2048; i += 256) o[i] = sacc[i];
}

__global__ void wreduce_kernel() {
    const int i = blockIdx.x * 256 + threadIdx.x;     // 0..32767
    const int b = i >> 11, k = i & 2047;
    float s = 0.0f;
#pragma unroll
    for (int j = 0; j < 16; j++) s += g_wp[((long long)b * 16 + j) * 2048 + k];
    g_w[i] = s;
}

// ---------------------------------------------------------------------------
// Final contraction, parallel over k-chunks.
// ---------------------------------------------------------------------------
__global__ void out_part_kernel() {
    const int b = blockIdx.x;
    const int kc = blockIdx.y;
    const int d = threadIdx.x;
    const float* w = g_w + b * 2048 + kc * 256;
    const float* v = g_v + ((long long)b * 2048 + kc * 256) * 256 + d;
    float acc = 0.0f;
#pragma unroll 8
    for (int k = 0; k < 256; k++)
        acc = fmaf(w[k], v[(long long)k * 256], acc);
    g_op[((long long)b * 8 + kc) * 256 + d] = acc;
}

__global__ void out_reduce_kernel(float* __restrict__ out) {
    const int b = blockIdx.x;
    const int d = threadIdx.x;
    float s = 0.0f;
#pragma unroll
    for (int j = 0; j < 8; j++) s += g_op[((long long)b * 8 + j) * 256 + d];
    out[b * 256 + d] = s;
}

// ---------------------------------------------------------------------------
extern "C" void kernel_launch(void* const* d_in, const int* in_sizes, int n_in,
                              void* d_out, int out_size) {
    (void)in_sizes; (void)n_in; (void)out_size;
    const float* x  = (const float*)d_in[0];
    const float* Wq = (const float*)d_in[1];
    const float* bq = (const float*)d_in[2];
    const float* Wk = (const float*)d_in[3];
    const float* bk = (const float*)d_in[4];
    const float* Wv = (const float*)d_in[5];
    const float* bv = (const float*)d_in[6];
    float* out = (float*)d_out;

    __half *pxh, *pwt, *pqs, *pks, *pe;
    float *pv;
    cudaGetSymbolAddress((void**)&pxh, g_xh);
    cudaGetSymbolAddress((void**)&pwt, g_wth);
    cudaGetSymbolAddress((void**)&pqs, g_qs);
    cudaGetSymbolAddress((void**)&pks, g_ks);
    cudaGetSymbolAddress((void**)&pv, g_v);
    cudaGetSymbolAddress((void**)&pe, g_energy);
    __half* pwtq = pwt;
    __half* pwtk = pwt + 256 * 256;
    __half* pwtv = pwt + 2 * 256 * 256;

    static int attr_done = 0;
    if (!attr_done) {
        cudaFuncSetAttribute(hmma_gemm<0>, cudaFuncAttributeMaxDynamicSharedMemorySize, SMEM_BYTES);
        cudaFuncSetAttribute(hmma_gemm<2>, cudaFuncAttributeMaxDynamicSharedMemorySize, SMEM_BYTES);
        attr_done = 1;
    }

    // 1) fp16 converts
    split_x_kernel<<<8192, 256>>>(x);
    split_w_kernel<<<dim3(256, 3), 256>>>(Wq, Wk, Wv);

    // 2) all projections in one launch: z = 0:q, 1:k, 2:v; K=256 1-term
    hmma_gemm<2><<<dim3(2, 256, 3), 256, SMEM_BYTES>>>(
        pxh, pwtq, pwtk, pwtv, bq, bk, bv, pv, pqs, pks, 0, 0, 1.0f);

    // 3) energy = q_hi k_hi^T / 16, batched, K=256
    hmma_gemm<0><<<dim3(16, 16, 16), 256, SMEM_BYTES>>>(
        pqs, pks, nullptr, nullptr, nullptr, nullptr, nullptr,
        nullptr, pe, nullptr,
        (long long)2048 * 256, (long long)2048 * 256, 0.0625f);

    // 4) fused softmax colsum (single pass, no max), reduce
    colsum_fused_kernel<<<dim3(16, 16), 256>>>();
    wreduce_kernel<<<128, 256>>>();

    // 5) final contraction
    out_part_kernel<<<dim3(16, 8), 256>>>();
    out_reduce_kernel<<<16, 256>>>(out);
}